// round 7
// baseline (speedup 1.0000x reference)
#include <cuda_runtime.h>

// Problem constants
#define NB 16
#define NC 3
#define H 768
#define W 768
#define HS 48            // H/16
#define WS 48            // W/16
#define NPIX (HS * WS)   // 2304
#define RADIUS 8

// Downsampled features: (f0, f1, f2, |f|^2) per (b, i). 16*2304*16B = 576 KB scratch.
__device__ float4 g_feats[NB * NPIX];

// ---------------------------------------------------------------------------
// Kernel 1: 16x bilinear downsample. Half-pixel centers => src = 16*i + 7.5,
// exact 0.5/0.5 weights => average of the 2x2 pixel block at (16y+7, 16x+7).
// Scalar loads only: x0 = 16*xi + 7 is ODD, so vector loads would misalign.
// ---------------------------------------------------------------------------
__global__ void resize_feats_kernel(const float* __restrict__ img) {
    int t = blockIdx.x * blockDim.x + threadIdx.x;
    if (t >= NB * NPIX) return;
    int b = t / NPIX;
    int i = t - b * NPIX;
    int yi = i / WS;
    int xi = i - yi * WS;
    int y0 = yi * 16 + 7;
    int x0 = xi * 16 + 7;

    float f[3];
#pragma unroll
    for (int c = 0; c < 3; ++c) {
        const float* p = img + ((size_t)(b * NC + c) * H + y0) * W + x0;
        // match separable resize: average rows first, then columns
        float r0 = 0.5f * (p[0] + p[1]);
        float r1 = 0.5f * (p[W] + p[W + 1]);
        f[c] = 0.5f * (r0 + r1);
    }
    float sq = f[0] * f[0] + f[1] * f[1] + f[2] * f[2];
    g_feats[t] = make_float4(f[0], f[1], f[2], sq);
}

// ---------------------------------------------------------------------------
// Kernel 2: affinity, row-loop form, register-resident fj (R5 base).
// Grid (144, 16, 2): block (bx, b, z) handles 8 rows
//   i = bx + (8*z + it)*144,  it = 0..7.
// Stride 144 == 3*WS, so xi is CONSTANT for the whole block; each thread's
// 4 j-columns (fj values, dx mask, dx^2) are tile-lifetime invariants.
// 4608 blocks at 2 blocks/SM -> ~15.6 waves: wave-quantization tail drops
// from ~16% (16-row / 5.2-wave version) to ~4%.
// One float4 (4 consecutive j) per thread; warp writes 512 contiguous bytes
// per row via streaming STG.128.
// ---------------------------------------------------------------------------
__global__ void __launch_bounds__(576) affinity_kernel(float* __restrict__ out) {
    const int q  = threadIdx.x;            // float4 index within row, 0..575
    const int bx = blockIdx.x;             // 0..143
    const int b  = blockIdx.y;             // 0..15
    const int z  = blockIdx.z;             // 0..1 (row-half)

    const int j0  = q * 4;
    const int yj  = q / 12;                // shared by the 4 j's (4 | 48)
    const int xj0 = j0 - yj * WS;
    const int xi  = bx - (bx / WS) * WS;   // constant across all rows of tile

    const float4* __restrict__ frow = g_feats + b * NPIX;

    // Tile-lifetime invariants: fj's, dx mask, 0.02*dx^2 term.
    float4 fj[4];
    float  sdx[4];
    bool   ok[4];
#pragma unroll
    for (int k = 0; k < 4; ++k) {
        const int dx = xi - (xj0 + k);
        ok[k]  = (dx >= -RADIUS) && (dx <= RADIUS);
        sdx[k] = 0.02f * (float)(dx * dx);
        fj[k]  = frow[j0 + k];
    }

    int i  = bx + z * 8 * 144;             // first row of this tile
    int dy = (bx / WS) + z * 24 - yj;      // its dy; +3 per iteration
    const float4 zero = make_float4(0.f, 0.f, 0.f, 0.f);
    float4* optr = (float4*)(out + (((size_t)b * NPIX + i) * NPIX)) + q;
    const size_t ostride = (size_t)144 * (NPIX / 4);   // float4s per 144 rows

#pragma unroll
    for (int it = 0; it < 8; ++it) {
        float4 v = zero;
        if (dy >= -RADIUS && dy <= RADIUS) {
            const float4 fi  = frow[i];
            const float  sdy = 0.02f * (float)(dy * dy);
            float* vv = (float*)&v;
#pragma unroll
            for (int k = 0; k < 4; ++k) {
                if (ok[k]) {
                    float cd = fi.w + fj[k].w
                             - 2.0f * (fi.x * fj[k].x + fi.y * fj[k].y + fi.z * fj[k].z);
                    cd = fmaxf(cd, 0.0f);
                    vv[k] = __expf(-(50.0f * cd + sdy + sdx[k]));
                }
            }
        }
        __stcs(optr, v);                   // streaming 128-bit store
        optr += ostride;
        i  += 144;
        dy += 3;
    }
}

// ---------------------------------------------------------------------------
extern "C" void kernel_launch(void* const* d_in, const int* in_sizes, int n_in,
                              void* d_out, int out_size) {
    const float* img = (const float*)d_in[0];
    float* out = (float*)d_out;

    const int nfeat = NB * NPIX;
    resize_feats_kernel<<<(nfeat + 255) / 256, 256>>>(img);

    dim3 grid(144, NB, 2);                 // 4608 blocks, 8 rows each
    affinity_kernel<<<grid, 576>>>(out);
}

// round 8
// speedup vs baseline: 1.2492x; 1.2492x over previous
#include <cuda_runtime.h>

// Problem constants
#define NB 16
#define NC 3
#define H 768
#define W 768
#define HS 48            // H/16
#define WS 48            // W/16
#define NPIX (HS * WS)   // 2304
#define RADIUS 8

// exp(-(50*cd + 0.02*sd)) = exp2( -LOG2E*(50*cd + 0.02*sd) )
#define C_DOT   144.269504089f   // 2*50*log2(e)
#define C_SQ     72.134752044f   // 50*log2(e)
#define C_SP      0.028853901f   // 0.02*log2(e)

// Downsampled features: (f0, f1, f2, |f|^2) per (b, i). 16*2304*16B = 576 KB scratch.
__device__ float4 g_feats[NB * NPIX];

// ---------------------------------------------------------------------------
// Kernel 1: 16x bilinear downsample. Half-pixel centers => src = 16*i + 7.5,
// exact 0.5/0.5 weights => average of the 2x2 pixel block at (16y+7, 16x+7).
// Scalar loads only: x0 = 16*xi + 7 is ODD, so vector loads would misalign.
// ---------------------------------------------------------------------------
__global__ void resize_feats_kernel(const float* __restrict__ img) {
    int t = blockIdx.x * blockDim.x + threadIdx.x;
    if (t >= NB * NPIX) return;
    int b = t / NPIX;
    int i = t - b * NPIX;
    int yi = i / WS;
    int xi = i - yi * WS;
    int y0 = yi * 16 + 7;
    int x0 = xi * 16 + 7;

    float f[3];
#pragma unroll
    for (int c = 0; c < 3; ++c) {
        const float* p = img + ((size_t)(b * NC + c) * H + y0) * W + x0;
        // match separable resize: average rows first, then columns
        float r0 = 0.5f * (p[0] + p[1]);
        float r1 = 0.5f * (p[W] + p[W + 1]);
        f[c] = 0.5f * (r0 + r1);
    }
    float sq = f[0] * f[0] + f[1] * f[1] + f[2] * f[2];
    g_feats[t] = make_float4(f[0], f[1], f[2], sq);
}

__device__ __forceinline__ float ex2(float x) {
    float r;
    asm("ex2.approx.ftz.f32 %0, %1;" : "=f"(r) : "f"(x));
    return r;
}

// ---------------------------------------------------------------------------
// Kernel 2: affinity, R5 geometry (best measured), EX2-folded math.
// Grid (144, 16): block bx handles rows i = bx, bx+144, ..., bx+15*144.
// Stride 144 == 3*WS, so xi is CONSTANT for the block; per-thread j-column
// invariants (pre-scaled fj', per-k exponent constant CK) computed once.
// Inner in-band work per k: 3 FMA + 1 FADD + 1 EX2.
//   t = 144.27*(fi.fj) - 72.13*(fi.w + fj.w) - 0.02886*(dy^2 + dx^2)
//   out = 2^t   (clamp on cd dropped: error <= ~5e-5 relative, budget 1e-3)
// ---------------------------------------------------------------------------
__global__ void __launch_bounds__(576) affinity_kernel(float* __restrict__ out) {
    const int q  = threadIdx.x;            // float4 index within row, 0..575
    const int bx = blockIdx.x;             // 0..143
    const int b  = blockIdx.y;             // 0..15

    const int j0  = q * 4;
    const int yj  = q / 12;                // shared by the 4 j's (4 | 48)
    const int xj0 = j0 - yj * WS;
    const int xi  = bx - (bx / WS) * WS;   // constant across all 16 rows

    const float4* __restrict__ frow = g_feats + b * NPIX;

    // Block-lifetime invariants: pre-scaled fj', per-k exponent constant, mask.
    float fjx[4], fjy[4], fjz[4], CK[4];
    bool  ok[4];
#pragma unroll
    for (int k = 0; k < 4; ++k) {
        const int dx = xi - (xj0 + k);
        ok[k] = (dx >= -RADIUS) && (dx <= RADIUS);
        const float4 fj = frow[j0 + k];
        fjx[k] = C_DOT * fj.x;
        fjy[k] = C_DOT * fj.y;
        fjz[k] = C_DOT * fj.z;
        CK[k]  = -C_SQ * fj.w - C_SP * (float)(dx * dx);
    }

    int yi = bx / WS;                      // row 0's grid-y; +3 per iteration
    const float4 zero = make_float4(0.f, 0.f, 0.f, 0.f);
    float4* optr = (float4*)(out + (((size_t)b * NPIX + bx) * NPIX)) + q;
    const size_t ostride = (size_t)144 * (NPIX / 4);   // float4s per 144 rows

    int i = bx;
#pragma unroll 4
    for (int it = 0; it < 16; ++it) {
        const int dy = yi - yj;
        float4 v = zero;
        if (dy >= -RADIUS && dy <= RADIUS) {
            const float4 fi = frow[i];
            const float  DI = -C_SQ * fi.w - C_SP * (float)(dy * dy);
            float* vv = (float*)&v;
#pragma unroll
            for (int k = 0; k < 4; ++k) {
                if (ok[k]) {
                    float t = fmaf(fjx[k], fi.x, CK[k]);
                    t = fmaf(fjy[k], fi.y, t);
                    t = fmaf(fjz[k], fi.z, t);
                    vv[k] = ex2(t + DI);
                }
            }
        }
        __stcs(optr, v);                   // streaming 128-bit store
        optr += ostride;
        i  += 144;
        yi += 3;
    }
}

// ---------------------------------------------------------------------------
extern "C" void kernel_launch(void* const* d_in, const int* in_sizes, int n_in,
                              void* d_out, int out_size) {
    const float* img = (const float*)d_in[0];
    float* out = (float*)d_out;

    const int nfeat = NB * NPIX;
    resize_feats_kernel<<<(nfeat + 255) / 256, 256>>>(img);

    dim3 grid(144, NB);                    // 2304 blocks, 16 rows each
    affinity_kernel<<<grid, 576>>>(out);
}